// round 1
// baseline (speedup 1.0000x reference)
#include <cuda_runtime.h>
#include <cstddef>

#define BATCH 32768
#define DIN   1024
#define ODIM  512
#define NFC   9
#define NCH   128                 // stats chunks
#define RPC   (BATCH / NCH)       // 256 rows per chunk
#define NSPL  8                   // split-B for Q^T K
#define BSPL  (BATCH / NSPL)      // 4096

// ---------------- scratch (device globals; no allocation allowed) ----------
__device__ float g_H[(size_t)NFC * BATCH * ODIM];          // 576 MB: H then (in-place) activated Q/K/V
__device__ float g_Psum[NFC * NCH * ODIM];
__device__ float g_Psq [NFC * NCH * ODIM];
__device__ float g_mu  [NFC * ODIM];
__device__ float g_rstd[NFC * ODIM];
__device__ float g_Spart[(size_t)3 * NSPL * ODIM * ODIM];  // 25 MB
__device__ float g_Attn [(size_t)3 * ODIM * ODIM];

// ---------------------------------------------------------------------------
// C[M x 512] = A[M x K] @ B[512 x K]^T (+ bias).  Both operands K-contiguous.
// 128x128 tile, BK=8, 256 threads, 8x8 per thread (4+64 split layout).
// ---------------------------------------------------------------------------
__global__ void __launch_bounds__(256)
gemm_nt(const float* __restrict__ A, const float* __restrict__ B,
        const float* __restrict__ bias, float* __restrict__ C, int K)
{
    __shared__ float As[8][128];
    __shared__ float Bs[8][128];

    const int tid = threadIdx.x;
    const int m0  = blockIdx.y * 128;
    const int n0  = blockIdx.x * 128;

    const int lr = tid >> 1;             // 0..127
    const int lk = (tid & 1) << 2;       // 0 or 4
    const float* Ap = A + (size_t)(m0 + lr) * K + lk;
    const float* Bp = B + (size_t)(n0 + lr) * K + lk;

    const int tm = (tid >> 4) << 2;      // 0..60
    const int tn = (tid & 15) << 2;      // 0..60

    float acc[8][8];
#pragma unroll
    for (int i = 0; i < 8; i++)
#pragma unroll
        for (int j = 0; j < 8; j++) acc[i][j] = 0.f;

    for (int k0 = 0; k0 < K; k0 += 8) {
        float4 av = *reinterpret_cast<const float4*>(Ap + k0);
        float4 bv = *reinterpret_cast<const float4*>(Bp + k0);
        __syncthreads();
        As[lk + 0][lr] = av.x; As[lk + 1][lr] = av.y;
        As[lk + 2][lr] = av.z; As[lk + 3][lr] = av.w;
        Bs[lk + 0][lr] = bv.x; Bs[lk + 1][lr] = bv.y;
        Bs[lk + 2][lr] = bv.z; Bs[lk + 3][lr] = bv.w;
        __syncthreads();
#pragma unroll
        for (int kk = 0; kk < 8; kk++) {
            float a[8], b[8];
            *reinterpret_cast<float4*>(&a[0]) = *reinterpret_cast<const float4*>(&As[kk][tm]);
            *reinterpret_cast<float4*>(&a[4]) = *reinterpret_cast<const float4*>(&As[kk][tm + 64]);
            *reinterpret_cast<float4*>(&b[0]) = *reinterpret_cast<const float4*>(&Bs[kk][tn]);
            *reinterpret_cast<float4*>(&b[4]) = *reinterpret_cast<const float4*>(&Bs[kk][tn + 64]);
#pragma unroll
            for (int i = 0; i < 8; i++)
#pragma unroll
                for (int j = 0; j < 8; j++)
                    acc[i][j] = fmaf(a[i], b[j], acc[i][j]);
        }
    }

    // epilogue
    const int c0 = n0 + tn;
    const int c1 = n0 + tn + 64;
    float b0[4] = {0.f, 0.f, 0.f, 0.f}, b1[4] = {0.f, 0.f, 0.f, 0.f};
    if (bias) {
#pragma unroll
        for (int j = 0; j < 4; j++) { b0[j] = bias[c0 + j]; b1[j] = bias[c1 + j]; }
    }
#pragma unroll
    for (int i = 0; i < 8; i++) {
        const int r = m0 + tm + (i < 4 ? i : 64 + (i - 4));
        float* Cp = C + (size_t)r * ODIM;
        float4 o0, o1;
        o0.x = acc[i][0] + b0[0]; o0.y = acc[i][1] + b0[1];
        o0.z = acc[i][2] + b0[2]; o0.w = acc[i][3] + b0[3];
        o1.x = acc[i][4] + b1[0]; o1.y = acc[i][5] + b1[1];
        o1.z = acc[i][6] + b1[2]; o1.w = acc[i][7] + b1[3];
        *reinterpret_cast<float4*>(Cp + c0) = o0;
        *reinterpret_cast<float4*>(Cp + c1) = o1;
    }
}

// ------------------- BN stats: stage 1 (deterministic chunk partials) ------
__global__ void __launch_bounds__(512)
stats1(const float* __restrict__ H)
{
    const int f = blockIdx.y, ch = blockIdx.x, c = threadIdx.x;
    const float* p = H + ((size_t)f * BATCH + (size_t)ch * RPC) * ODIM + c;
    float s = 0.f, q = 0.f;
#pragma unroll 4
    for (int r = 0; r < RPC; r++) {
        float v = p[(size_t)r * ODIM];
        s += v;
        q = fmaf(v, v, q);
    }
    g_Psum[(f * NCH + ch) * ODIM + c] = s;
    g_Psq [(f * NCH + ch) * ODIM + c] = q;
}

// ------------------- BN stats: stage 2 (serial reduce -> mu, rstd) ---------
__global__ void __launch_bounds__(512)
stats2()
{
    const int f = blockIdx.x, c = threadIdx.x;
    float s = 0.f, q = 0.f;
    for (int ch = 0; ch < NCH; ch++) {
        s += g_Psum[(f * NCH + ch) * ODIM + c];
        q += g_Psq [(f * NCH + ch) * ODIM + c];
    }
    const float mu  = s * (1.f / BATCH);
    const float var = q * (1.f / BATCH) - mu * mu;
    g_mu  [f * ODIM + c] = mu;
    g_rstd[f * ODIM + c] = rsqrtf(var + 1e-5f);
}

// ------------------- BN + ReLU, in place over all 9 FC outputs -------------
__global__ void __launch_bounds__(256)
bn_relu(float* __restrict__ H, const float* __restrict__ gammas,
        const float* __restrict__ betas)
{
    const size_t idx = (size_t)blockIdx.x * 256 + threadIdx.x;  // float4 index
    const int c = (int)((idx << 2) & (ODIM - 1));
    const int f = (int)(idx >> 22);                              // BATCH*ODIM/4 = 2^22
    float4 h = reinterpret_cast<float4*>(H)[idx];
    const float* mu = g_mu   + f * ODIM + c;
    const float* rs = g_rstd + f * ODIM + c;
    const float* ga = gammas + (size_t)f * ODIM + c;
    const float* be = betas  + (size_t)f * ODIM + c;
    h.x = fmaxf(fmaf((h.x - mu[0]) * rs[0], ga[0], be[0]), 0.f);
    h.y = fmaxf(fmaf((h.y - mu[1]) * rs[1], ga[1], be[1]), 0.f);
    h.z = fmaxf(fmaf((h.z - mu[2]) * rs[2], ga[2], be[2]), 0.f);
    h.w = fmaxf(fmaf((h.w - mu[3]) * rs[3], ga[3], be[3]), 0.f);
    reinterpret_cast<float4*>(H)[idx] = h;
}

// ------------------- S_part = Q^T K (split over batch, deterministic) ------
__global__ void __launch_bounds__(256)
qtk_gemm(const float* __restrict__ Q, const float* __restrict__ Kmat,
         float* __restrict__ Spart)
{
    __shared__ float Qs[16][64];
    __shared__ float Ks[16][64];
    const int tid = threadIdx.x;
    const int i0 = blockIdx.x * 64, j0 = blockIdx.y * 64;
    const int sp = blockIdx.z;

    const int br = tid >> 4;             // 0..15
    const int ic = (tid & 15) << 2;      // 0..60
    const float* Qp = Q    + ((size_t)sp * BSPL + br) * ODIM + i0 + ic;
    const float* Kp = Kmat + ((size_t)sp * BSPL + br) * ODIM + j0 + ic;

    const int ti = (tid >> 4) << 2;      // 0..60
    const int tj = (tid & 15) << 2;      // 0..60

    float acc[4][4];
#pragma unroll
    for (int i = 0; i < 4; i++)
#pragma unroll
        for (int j = 0; j < 4; j++) acc[i][j] = 0.f;

    for (int b0 = 0; b0 < BSPL; b0 += 16) {
        float4 qv = *reinterpret_cast<const float4*>(Qp + (size_t)b0 * ODIM);
        float4 kv = *reinterpret_cast<const float4*>(Kp + (size_t)b0 * ODIM);
        __syncthreads();
        *reinterpret_cast<float4*>(&Qs[br][ic]) = qv;
        *reinterpret_cast<float4*>(&Ks[br][ic]) = kv;
        __syncthreads();
#pragma unroll
        for (int kk = 0; kk < 16; kk++) {
            float q[4], k[4];
            *reinterpret_cast<float4*>(q) = *reinterpret_cast<const float4*>(&Qs[kk][ti]);
            *reinterpret_cast<float4*>(k) = *reinterpret_cast<const float4*>(&Ks[kk][tj]);
#pragma unroll
            for (int i = 0; i < 4; i++)
#pragma unroll
                for (int j = 0; j < 4; j++)
                    acc[i][j] = fmaf(q[i], k[j], acc[i][j]);
        }
    }

    float* Sp = Spart + ((size_t)sp * ODIM + i0 + ti) * ODIM + j0 + tj;
#pragma unroll
    for (int i = 0; i < 4; i++) {
        float4 o;
        o.x = acc[i][0]; o.y = acc[i][1]; o.z = acc[i][2]; o.w = acc[i][3];
        *reinterpret_cast<float4*>(Sp + (size_t)i * ODIM) = o;
    }
}

// ------------- reduce split partials + softmax over rows (axis=1) ----------
__global__ void __launch_bounds__(256)
softmax_rows()
{
    const int i = blockIdx.x, a = blockIdx.y, tid = threadIdx.x;
    __shared__ float red[256];

    const float* Sp = g_Spart + (size_t)a * NSPL * ODIM * ODIM + (size_t)i * ODIM;
    float v0 = 0.f, v1 = 0.f;
#pragma unroll
    for (int s = 0; s < NSPL; s++) {
        v0 += Sp[(size_t)s * ODIM * ODIM + tid];
        v1 += Sp[(size_t)s * ODIM * ODIM + tid + 256];
    }
    v0 *= 0.03125f;  // 1/sqrt(1024)
    v1 *= 0.03125f;

    red[tid] = fmaxf(v0, v1);
    __syncthreads();
    for (int o = 128; o > 0; o >>= 1) {
        if (tid < o) red[tid] = fmaxf(red[tid], red[tid + o]);
        __syncthreads();
    }
    const float m = red[0];
    __syncthreads();

    const float e0 = expf(v0 - m), e1 = expf(v1 - m);
    red[tid] = e0 + e1;
    __syncthreads();
    for (int o = 128; o > 0; o >>= 1) {
        if (tid < o) red[tid] += red[tid + o];
        __syncthreads();
    }
    const float inv = 1.f / red[0];

    float* Ap = g_Attn + (size_t)a * ODIM * ODIM + (size_t)i * ODIM;
    Ap[tid]       = e0 * inv;
    Ap[tid + 256] = e1 * inv;
}

// ---------------------------------------------------------------------------
extern "C" void kernel_launch(void* const* d_in, const int* in_sizes, int n_in,
                              void* d_out, int out_size)
{
    (void)in_sizes; (void)n_in; (void)out_size;
    const float* X[3] = { (const float*)d_in[0],   // cx
                          (const float*)d_in[1],   // gx
                          (const float*)d_in[2] }; // wx
    const float* Ws     = (const float*)d_in[3];
    const float* bs     = (const float*)d_in[4];
    const float* gammas = (const float*)d_in[5];
    const float* betas  = (const float*)d_in[6];
    float* out = (float*)d_out;

    float *Hp = nullptr, *Spartp = nullptr, *Attnp = nullptr;
    cudaGetSymbolAddress((void**)&Hp,     g_H);
    cudaGetSymbolAddress((void**)&Spartp, g_Spart);
    cudaGetSymbolAddress((void**)&Attnp,  g_Attn);

    // FC input mapping: attn a uses (x1, x2): 0:(cx,gx) 1:(gx,wx) 2:(wx,cx)
    // f = 3a (Q <- x1), 3a+1 (K <- x2), 3a+2 (V <- x2)
    const int xidx[NFC] = {0, 1, 1, 1, 2, 2, 2, 0, 0};

    dim3 gG(ODIM / 128, BATCH / 128);  // (4, 256)

    for (int f = 0; f < NFC; f++) {
        gemm_nt<<<gG, 256>>>(X[xidx[f]],
                             Ws + (size_t)f * ODIM * DIN,
                             bs + (size_t)f * ODIM,
                             Hp + (size_t)f * BATCH * ODIM,
                             DIN);
    }

    stats1<<<dim3(NCH, NFC), 512>>>(Hp);
    stats2<<<NFC, 512>>>();

    const int n4 = (int)(((size_t)NFC * BATCH * ODIM / 4) / 256);  // 147456
    bn_relu<<<n4, 256>>>(Hp, gammas, betas);

    for (int a = 0; a < 3; a++) {
        qtk_gemm<<<dim3(ODIM / 64, ODIM / 64, NSPL), 256>>>(
            Hp + (size_t)(3 * a)     * BATCH * ODIM,
            Hp + (size_t)(3 * a + 1) * BATCH * ODIM,
            Spartp + (size_t)a * NSPL * ODIM * ODIM);
    }

    softmax_rows<<<dim3(ODIM, 3), 256>>>();

    for (int a = 0; a < 3; a++) {
        gemm_nt<<<gG, 256>>>(Hp + (size_t)(3 * a + 2) * BATCH * ODIM,
                             Attnp + (size_t)a * ODIM * ODIM,
                             nullptr,
                             out + (size_t)a * BATCH * ODIM,
                             ODIM);
    }
}

// round 3
// speedup vs baseline: 2.7100x; 2.7100x over previous
#include <cuda_runtime.h>
#include <cuda_bf16.h>
#include <cstdint>
#include <cstddef>

#define B_    32768
#define XK    1024
#define OD    512
#define NFC   9
#define NCH   128
#define RPC   (B_ / NCH)
#define NSPL  16

// ------------------------- scratch (device globals) ------------------------
__device__ __align__(128) float g_H[(size_t)NFC * B_ * OD];
__device__ __align__(128) __nv_bfloat16 g_Xhi[(size_t)3 * B_ * XK], g_Xlo[(size_t)3 * B_ * XK];
__device__ __align__(128) __nv_bfloat16 g_Whi[(size_t)NFC * OD * XK], g_Wlo[(size_t)NFC * OD * XK];
__device__ __align__(128) __nv_bfloat16 g_Phi[(size_t)NFC * B_ * OD], g_Plo[(size_t)NFC * B_ * OD];
__device__ __align__(128) __nv_bfloat16 g_Thi[(size_t)6 * OD * B_], g_Tlo[(size_t)6 * OD * B_];
__device__ __align__(128) float g_Spart[(size_t)3 * NSPL * OD * OD];
__device__ __align__(128) __nv_bfloat16 g_Athi[(size_t)3 * OD * OD], g_Atlo[(size_t)3 * OD * OD];
__device__ float g_Psum[NFC * NCH * OD], g_Psq[NFC * NCH * OD];
__device__ float g_mu[NFC * OD], g_rstd[NFC * OD];

// ------------------------------ PTX helpers --------------------------------
__device__ __forceinline__ uint32_t smem_u32(const void* p) {
    uint32_t a;
    asm("{ .reg .u64 t; cvta.to.shared.u64 t, %1; cvt.u32.u64 %0, t; }" : "=r"(a) : "l"(p));
    return a;
}
__device__ __forceinline__ void cp16(uint32_t sa, const void* g) {
    asm volatile("cp.async.cg.shared.global [%0], [%1], 16;" :: "r"(sa), "l"(g));
}
#define CP_COMMIT() asm volatile("cp.async.commit_group;" ::: "memory")

#define LDSM_X4(r, a) asm volatile(                                          \
    "ldmatrix.sync.aligned.m8n8.x4.shared.b16 {%0,%1,%2,%3}, [%4];"          \
    : "=r"((r)[0]), "=r"((r)[1]), "=r"((r)[2]), "=r"((r)[3]) : "r"(a))

__device__ __forceinline__ void mma16816(float* d, const uint32_t* a,
                                         uint32_t b0, uint32_t b1) {
    asm volatile(
        "mma.sync.aligned.m16n8k16.row.col.f32.bf16.bf16.f32 "
        "{%0,%1,%2,%3}, {%4,%5,%6,%7}, {%8,%9}, {%0,%1,%2,%3};"
        : "+f"(d[0]), "+f"(d[1]), "+f"(d[2]), "+f"(d[3])
        : "r"(a[0]), "r"(a[1]), "r"(a[2]), "r"(a[3]), "r"(b0), "r"(b1));
}

// --------------------------- HMMA 3-split GEMM ------------------------------
// C[M x N] (fp32) = (Ahi+Alo)[M x K] @ (Bhi+Blo)[N x K]^T  (lo*lo dropped)
// CTA tile 128x128, BK=64, 8 warps (warp tile 64x32), 2-stage cp.async.
// smem stage (64 KB): Ahi@0, Alo@16K, Bhi@32K, Blo@48K; 128B rows, xor-swizzled.
#define STG_SZ 65536
#define GEMM_SMEM (2 * STG_SZ)

__device__ __forceinline__ void load_chunk(
    uint32_t st, const __nv_bfloat16* __restrict__ Ah,
    const __nv_bfloat16* __restrict__ Al,
    const __nv_bfloat16* __restrict__ Bh,
    const __nv_bfloat16* __restrict__ Bl,
    size_t lda, size_t ldb, int m0, int n0, size_t kofs, int tid)
{
    const int ck = tid & 7;              // 16B chunk in 128B row
    const int r0 = tid >> 3;             // 0..31
    const size_t co = kofs + (size_t)(ck << 3);
#pragma unroll
    for (int r = r0; r < 128; r += 32) {
        const uint32_t so = (uint32_t)(r * 128 + ((ck ^ (r & 7)) << 4));
        const size_t ga = (size_t)(m0 + r) * lda + co;
        const size_t gb = (size_t)(n0 + r) * ldb + co;
        cp16(st + so,         Ah + ga);
        cp16(st + 16384 + so, Al + ga);
        cp16(st + 32768 + so, Bh + gb);
        cp16(st + 49152 + so, Bl + gb);
    }
    CP_COMMIT();
}

__global__ void __launch_bounds__(256, 1)
gemm_mma(const __nv_bfloat16* __restrict__ Ahi, const __nv_bfloat16* __restrict__ Alo,
         const __nv_bfloat16* __restrict__ Bhi, const __nv_bfloat16* __restrict__ Blo,
         float* __restrict__ C,
         size_t lda, size_t ldb, size_t ldc,
         int nkc, size_t kper_z, size_t csplit)
{
    extern __shared__ char smem[];
    const uint32_t sb = smem_u32(smem);
    const int tid  = threadIdx.x;
    const int wid  = tid >> 5, lane = tid & 31;
    const int m0   = blockIdx.y * 128;
    const int n0   = blockIdx.x * 128;
    const size_t kbase = (size_t)blockIdx.z * kper_z;
    C += (size_t)blockIdx.z * csplit;

    const int wm = (wid & 1) * 64;       // warp m offset (2)
    const int wn = (wid >> 1) * 32;      // warp n offset (4)

    // per-lane ldmatrix row geometry (chunk index varies per kk)
    int aRow[4], aSw[4];
#pragma unroll
    for (int mt = 0; mt < 4; mt++) {
        aRow[mt] = wm + mt * 16 + (lane & 15);
        aSw[mt]  = aRow[mt] & 7;
    }
    const int ackL = lane >> 4;          // 0/1: k chunk within 16
    int bRow[2], bSw[2];
#pragma unroll
    for (int np = 0; np < 2; np++) {
        bRow[np] = wn + np * 16 + (lane & 7) + ((lane >> 4) << 3);
        bSw[np]  = bRow[np] & 7;
    }
    const int bckL = (lane >> 3) & 1;

    float acc[4][4][4];
#pragma unroll
    for (int i = 0; i < 4; i++)
#pragma unroll
        for (int j = 0; j < 4; j++)
#pragma unroll
            for (int e = 0; e < 4; e++) acc[i][j][e] = 0.f;

    load_chunk(sb,          Ahi, Alo, Bhi, Blo, lda, ldb, m0, n0, kbase,      tid);
    load_chunk(sb + STG_SZ, Ahi, Alo, Bhi, Blo, lda, ldb, m0, n0, kbase + 64, tid);

#pragma unroll 1
    for (int c = 0; c < nkc; c++) {
        if (c + 1 < nkc) asm volatile("cp.async.wait_group 1;" ::: "memory");
        else             asm volatile("cp.async.wait_group 0;" ::: "memory");
        __syncthreads();

        const uint32_t stA = sb + (uint32_t)(c & 1) * STG_SZ;
        const uint32_t stB = stA + 32768;

#pragma unroll
        for (int kk = 0; kk < 4; kk++) {
            uint32_t ah[4][4], al[4][4];
#pragma unroll
            for (int mt = 0; mt < 4; mt++) {
                const uint32_t co = (uint32_t)(((2 * kk + ackL) ^ aSw[mt]) << 4);
                const uint32_t ad = stA + (uint32_t)(aRow[mt] * 128) + co;
                LDSM_X4(ah[mt], ad);
                LDSM_X4(al[mt], ad + 16384);
            }
            uint32_t bh[2][4], bl[2][4];
#pragma unroll
            for (int np = 0; np < 2; np++) {
                const uint32_t co = (uint32_t)(((2 * kk + bckL) ^ bSw[np]) << 4);
                const uint32_t bd = stB + (uint32_t)(bRow[np] * 128) + co;
                LDSM_X4(bh[np], bd);
                LDSM_X4(bl[np], bd + 16384);
            }
#pragma unroll
            for (int mt = 0; mt < 4; mt++)
#pragma unroll
                for (int nt = 0; nt < 4; nt++) {
                    const int np = nt >> 1, h = (nt & 1) * 2;
                    mma16816(acc[mt][nt], ah[mt], bh[np][h], bh[np][h + 1]);
                    mma16816(acc[mt][nt], ah[mt], bl[np][h], bl[np][h + 1]);
                    mma16816(acc[mt][nt], al[mt], bh[np][h], bh[np][h + 1]);
                }
        }

        __syncthreads();
        if (c + 2 < nkc)
            load_chunk(sb + (uint32_t)(c & 1) * STG_SZ, Ahi, Alo, Bhi, Blo,
                       lda, ldb, m0, n0, kbase + (size_t)(c + 2) * 64, tid);
    }

    // epilogue: direct fp32 stores (thread frag mapping of m16n8)
    const int re = lane >> 2;
    const int ce = (lane & 3) * 2;
#pragma unroll
    for (int mt = 0; mt < 4; mt++) {
#pragma unroll
        for (int nt = 0; nt < 4; nt++) {
            const size_t r  = (size_t)(m0 + wm + mt * 16 + re);
            const size_t cc = (size_t)(n0 + wn + nt * 8 + ce);
            float2 v0 = make_float2(acc[mt][nt][0], acc[mt][nt][1]);
            float2 v1 = make_float2(acc[mt][nt][2], acc[mt][nt][3]);
            *reinterpret_cast<float2*>(C + r * ldc + cc)       = v0;
            *reinterpret_cast<float2*>(C + (r + 8) * ldc + cc) = v1;
        }
    }
}

// ----------------------- fp32 -> bf16 hi/lo split ---------------------------
__global__ void __launch_bounds__(256)
split_planes(const float4* __restrict__ in, __nv_bfloat162* __restrict__ hi,
             __nv_bfloat162* __restrict__ lo, int n4)
{
    int i = blockIdx.x * 256 + threadIdx.x;
    if (i >= n4) return;
    float4 v = in[i];
    __nv_bfloat16 h0 = __float2bfloat16_rn(v.x), h1 = __float2bfloat16_rn(v.y);
    __nv_bfloat16 h2 = __float2bfloat16_rn(v.z), h3 = __float2bfloat16_rn(v.w);
    __nv_bfloat16 l0 = __float2bfloat16_rn(v.x - __bfloat162float(h0));
    __nv_bfloat16 l1 = __float2bfloat16_rn(v.y - __bfloat162float(h1));
    __nv_bfloat16 l2 = __float2bfloat16_rn(v.z - __bfloat162float(h2));
    __nv_bfloat16 l3 = __float2bfloat16_rn(v.w - __bfloat162float(h3));
    hi[2 * i]     = __halves2bfloat162(h0, h1);
    hi[2 * i + 1] = __halves2bfloat162(h2, h3);
    lo[2 * i]     = __halves2bfloat162(l0, l1);
    lo[2 * i + 1] = __halves2bfloat162(l2, l3);
}

// ------------------------------ BN stats ------------------------------------
__global__ void __launch_bounds__(512)
stats1(const float* __restrict__ H)
{
    const int f = blockIdx.y, ch = blockIdx.x, c = threadIdx.x;
    const float* p = H + ((size_t)f * B_ + (size_t)ch * RPC) * OD + c;
    float s = 0.f, q = 0.f;
#pragma unroll 4
    for (int r = 0; r < RPC; r++) {
        float v = p[(size_t)r * OD];
        s += v;
        q = fmaf(v, v, q);
    }
    g_Psum[(f * NCH + ch) * OD + c] = s;
    g_Psq [(f * NCH + ch) * OD + c] = q;
}

__global__ void __launch_bounds__(512)
stats2()
{
    const int f = blockIdx.x, c = threadIdx.x;
    float s = 0.f, q = 0.f;
    for (int ch = 0; ch < NCH; ch++) {
        s += g_Psum[(f * NCH + ch) * OD + c];
        q += g_Psq [(f * NCH + ch) * OD + c];
    }
    const float mu  = s * (1.f / B_);
    const float var = q * (1.f / B_) - mu * mu;
    g_mu  [f * OD + c] = mu;
    g_rstd[f * OD + c] = rsqrtf(var + 1e-5f);
}

// ---------------- BN + ReLU -> bf16 hi/lo planes ----------------------------
__global__ void __launch_bounds__(256)
bn_relu_split(const float* __restrict__ H, const float* __restrict__ gammas,
              const float* __restrict__ betas,
              __nv_bfloat162* __restrict__ Phi, __nv_bfloat162* __restrict__ Plo)
{
    const size_t idx = (size_t)blockIdx.x * 256 + threadIdx.x;  // float4 index
    const int c = (int)((idx << 2) & (OD - 1));
    const int f = (int)(idx >> 22);
    float4 h = reinterpret_cast<const float4*>(H)[idx];
    const float* mu = g_mu   + f * OD + c;
    const float* rs = g_rstd + f * OD + c;
    const float* ga = gammas + (size_t)f * OD + c;
    const float* be = betas  + (size_t)f * OD + c;
    float v0 = fmaxf(fmaf((h.x - mu[0]) * rs[0], ga[0], be[0]), 0.f);
    float v1 = fmaxf(fmaf((h.y - mu[1]) * rs[1], ga[1], be[1]), 0.f);
    float v2 = fmaxf(fmaf((h.z - mu[2]) * rs[2], ga[2], be[2]), 0.f);
    float v3 = fmaxf(fmaf((h.w - mu[3]) * rs[3], ga[3], be[3]), 0.f);
    __nv_bfloat16 h0 = __float2bfloat16_rn(v0), h1 = __float2bfloat16_rn(v1);
    __nv_bfloat16 h2 = __float2bfloat16_rn(v2), h3 = __float2bfloat16_rn(v3);
    __nv_bfloat16 l0 = __float2bfloat16_rn(v0 - __bfloat162float(h0));
    __nv_bfloat16 l1 = __float2bfloat16_rn(v1 - __bfloat162float(h1));
    __nv_bfloat16 l2 = __float2bfloat16_rn(v2 - __bfloat162float(h2));
    __nv_bfloat16 l3 = __float2bfloat16_rn(v3 - __bfloat162float(h3));
    Phi[2 * idx]     = __halves2bfloat162(h0, h1);
    Phi[2 * idx + 1] = __halves2bfloat162(h2, h3);
    Plo[2 * idx]     = __halves2bfloat162(l0, l1);
    Plo[2 * idx + 1] = __halves2bfloat162(l2, l3);
}

// -------------------- transpose planes: [B,512] -> [512,B] ------------------
__global__ void __launch_bounds__(256)
transpose_pl()
{
    __shared__ __nv_bfloat16 t[32][33];
    const int z = blockIdx.z;             // 0..11
    const int slot = z >> 1, pl = z & 1;
    const int f = slot + (slot >> 1);     // {0,1,3,4,6,7}
    const __nv_bfloat16* src = (pl ? g_Plo : g_Phi) + (size_t)f * B_ * OD;
    __nv_bfloat16* dst = (pl ? g_Tlo : g_Thi) + (size_t)slot * OD * B_;
    const int c0 = blockIdx.x * 32;
    const size_t b0 = (size_t)blockIdx.y * 32;
    const int tx = threadIdx.x, ty = threadIdx.y;
#pragma unroll
    for (int i = 0; i < 32; i += 8)
        t[ty + i][tx] = src[(b0 + ty + i) * OD + c0 + tx];
    __syncthreads();
#pragma unroll
    for (int i = 0; i < 32; i += 8)
        dst[(size_t)(c0 + ty + i) * B_ + b0 + tx] = t[tx][ty + i];
}

// --------- reduce split-K partials + row softmax -> attn bf16 planes --------
__global__ void __launch_bounds__(256)
softmax_rows()
{
    const int i = blockIdx.x, a = blockIdx.y, tid = threadIdx.x;
    __shared__ float red[256];

    const float* Sp = g_Spart + (size_t)a * NSPL * OD * OD + (size_t)i * OD;
    float v0 = 0.f, v1 = 0.f;
#pragma unroll
    for (int s = 0; s < NSPL; s++) {
        v0 += Sp[(size_t)s * OD * OD + tid];
        v1 += Sp[(size_t)s * OD * OD + tid + 256];
    }
    v0 *= 0.03125f;  // 1/sqrt(1024)
    v1 *= 0.03125f;

    red[tid] = fmaxf(v0, v1);
    __syncthreads();
    for (int o = 128; o > 0; o >>= 1) {
        if (tid < o) red[tid] = fmaxf(red[tid], red[tid + o]);
        __syncthreads();
    }
    const float m = red[0];
    __syncthreads();
    const float e0 = expf(v0 - m), e1 = expf(v1 - m);
    red[tid] = e0 + e1;
    __syncthreads();
    for (int o = 128; o > 0; o >>= 1) {
        if (tid < o) red[tid] += red[tid + o];
        __syncthreads();
    }
    const float inv = 1.f / red[0];
    const float p0 = e0 * inv, p1 = e1 * inv;

    const size_t base = (size_t)a * OD * OD + (size_t)i * OD;
    __nv_bfloat16 h0 = __float2bfloat16_rn(p0), h1 = __float2bfloat16_rn(p1);
    g_Athi[base + tid]       = h0;
    g_Athi[base + tid + 256] = h1;
    g_Atlo[base + tid]       = __float2bfloat16_rn(p0 - __bfloat162float(h0));
    g_Atlo[base + tid + 256] = __float2bfloat16_rn(p1 - __bfloat162float(h1));
}

// ---------------------------------------------------------------------------
extern "C" void kernel_launch(void* const* d_in, const int* in_sizes, int n_in,
                              void* d_out, int out_size)
{
    (void)in_sizes; (void)n_in; (void)out_size;
    const float* X[3] = { (const float*)d_in[0], (const float*)d_in[1],
                          (const float*)d_in[2] };
    const float* Ws     = (const float*)d_in[3];
    const float* gammas = (const float*)d_in[5];
    const float* betas  = (const float*)d_in[6];
    float* out = (float*)d_out;

    float *Hp = nullptr, *Spartp = nullptr;
    __nv_bfloat16 *Xhi, *Xlo, *Whi, *Wlo, *Phi, *Plo, *Thi, *Tlo, *Athi, *Atlo;
    cudaGetSymbolAddress((void**)&Hp, g_H);
    cudaGetSymbolAddress((void**)&Spartp, g_Spart);
    cudaGetSymbolAddress((void**)&Xhi, g_Xhi);
    cudaGetSymbolAddress((void**)&Xlo, g_Xlo);
    cudaGetSymbolAddress((void**)&Whi, g_Whi);
    cudaGetSymbolAddress((void**)&Wlo, g_Wlo);
    cudaGetSymbolAddress((void**)&Phi, g_Phi);
    cudaGetSymbolAddress((void**)&Plo, g_Plo);
    cudaGetSymbolAddress((void**)&Thi, g_Thi);
    cudaGetSymbolAddress((void**)&Tlo, g_Tlo);
    cudaGetSymbolAddress((void**)&Athi, g_Athi);
    cudaGetSymbolAddress((void**)&Atlo, g_Atlo);

    cudaFuncSetAttribute(gemm_mma, cudaFuncAttributeMaxDynamicSharedMemorySize, GEMM_SMEM);

    const size_t XSZ = (size_t)B_ * XK;
    const size_t WSZ = (size_t)OD * XK;
    const size_t PSZ = (size_t)B_ * OD;
    const size_t TSZ = (size_t)OD * B_;

    // 1. split inputs + weights to bf16 hi/lo planes
    {
        int n4 = (int)(XSZ / 4);
        for (int i = 0; i < 3; i++)
            split_planes<<<(n4 + 255) / 256, 256>>>(
                (const float4*)X[i], (__nv_bfloat162*)(Xhi + i * XSZ),
                (__nv_bfloat162*)(Xlo + i * XSZ), n4);
        int w4 = (int)((size_t)NFC * WSZ / 4);
        split_planes<<<(w4 + 255) / 256, 256>>>(
            (const float4*)Ws, (__nv_bfloat162*)Whi, (__nv_bfloat162*)Wlo, w4);
    }

    // 2. nine FC GEMMs: H[f] = X[xi] @ W[f]^T   (bias cancels in BN)
    const int xidx[NFC] = {0, 1, 1, 1, 2, 2, 2, 0, 0};
    for (int f = 0; f < NFC; f++) {
        gemm_mma<<<dim3(OD / 128, B_ / 128, 1), 256, GEMM_SMEM>>>(
            Xhi + (size_t)xidx[f] * XSZ, Xlo + (size_t)xidx[f] * XSZ,
            Whi + (size_t)f * WSZ, Wlo + (size_t)f * WSZ,
            Hp + (size_t)f * PSZ,
            XK, XK, OD, XK / 64, 0, 0);
    }

    // 3. BN stats + BN/ReLU -> bf16 planes
    stats1<<<dim3(NCH, NFC), 512>>>(Hp);
    stats2<<<NFC, 512>>>();
    {
        int n4 = (int)((size_t)NFC * PSZ / 4);
        bn_relu_split<<<n4 / 256, 256>>>(Hp, gammas, betas,
                                         (__nv_bfloat162*)Phi, (__nv_bfloat162*)Plo);
    }

    // 4. transpose Q,K planes to [512, B]
    transpose_pl<<<dim3(OD / 32, B_ / 32, 12), dim3(32, 8)>>>();

    // 5. S = Q^T K with split-K(16) -> Spart
    for (int a = 0; a < 3; a++) {
        gemm_mma<<<dim3(OD / 128, OD / 128, NSPL), 256, GEMM_SMEM>>>(
            Thi + (size_t)(2 * a) * TSZ, Tlo + (size_t)(2 * a) * TSZ,
            Thi + (size_t)(2 * a + 1) * TSZ, Tlo + (size_t)(2 * a + 1) * TSZ,
            Spartp + (size_t)a * NSPL * OD * OD,
            B_, B_, OD, (B_ / NSPL) / 64, B_ / NSPL, (size_t)OD * OD);
    }

    // 6. softmax (reduces 16 partials) -> attn bf16 planes
    softmax_rows<<<dim3(OD, 3), 256>>>();

    // 7. out[a] = V @ attn^T
    for (int a = 0; a < 3; a++) {
        gemm_mma<<<dim3(OD / 128, B_ / 128, 1), 256, GEMM_SMEM>>>(
            Phi + (size_t)(3 * a + 2) * PSZ, Plo + (size_t)(3 * a + 2) * PSZ,
            Athi + (size_t)a * OD * OD, Atlo + (size_t)a * OD * OD,
            out + (size_t)a * PSZ,
            OD, OD, OD, OD / 64, 0, 0);
    }
}

// round 4
// speedup vs baseline: 3.1733x; 1.1709x over previous
#include <cuda_runtime.h>
#include <cuda_bf16.h>
#include <cstdint>
#include <cstddef>

#define B_    32768
#define XK    1024
#define OD    512
#define NFC   9
#define NSPL  16

// ------------------------- scratch (device globals) ------------------------
__device__ __align__(128) float g_H[(size_t)NFC * B_ * OD];
__device__ __align__(128) __nv_bfloat16 g_Xhi[(size_t)3 * B_ * XK], g_Xlo[(size_t)3 * B_ * XK];
__device__ __align__(128) __nv_bfloat16 g_Whi[(size_t)NFC * OD * XK], g_Wlo[(size_t)NFC * OD * XK];
__device__ __align__(128) __nv_bfloat16 g_Phi[(size_t)NFC * B_ * OD], g_Plo[(size_t)NFC * B_ * OD];
__device__ __align__(128) __nv_bfloat16 g_Thi[(size_t)6 * OD * B_], g_Tlo[(size_t)6 * OD * B_];
__device__ __align__(128) float g_Spart[(size_t)3 * NSPL * OD * OD];
__device__ __align__(128) __nv_bfloat16 g_Athi[(size_t)3 * OD * OD], g_Atlo[(size_t)3 * OD * OD];
__device__ __align__(128) float g_Pstat[(size_t)NFC * 256 * 4 * 256]; // [f][my][nx][{s,q}x128]
__device__ float g_mu[NFC * OD], g_rstd[NFC * OD];

// ------------------------------ PTX helpers --------------------------------
__device__ __forceinline__ uint32_t smem_u32(const void* p) {
    uint32_t a;
    asm("{ .reg .u64 t; cvta.to.shared.u64 t, %1; cvt.u32.u64 %0, t; }" : "=r"(a) : "l"(p));
    return a;
}
__device__ __forceinline__ void cp16(uint32_t sa, const void* g) {
    asm volatile("cp.async.cg.shared.global [%0], [%1], 16;" :: "r"(sa), "l"(g));
}
#define CP_COMMIT() asm volatile("cp.async.commit_group;" ::: "memory")

#define LDSM_X4(r, a) asm volatile(                                          \
    "ldmatrix.sync.aligned.m8n8.x4.shared.b16 {%0,%1,%2,%3}, [%4];"          \
    : "=r"((r)[0]), "=r"((r)[1]), "=r"((r)[2]), "=r"((r)[3]) : "r"(a))

__device__ __forceinline__ void mma16816(float* d, const uint32_t* a,
                                         uint32_t b0, uint32_t b1) {
    asm volatile(
        "mma.sync.aligned.m16n8k16.row.col.f32.bf16.bf16.f32 "
        "{%0,%1,%2,%3}, {%4,%5,%6,%7}, {%8,%9}, {%0,%1,%2,%3};"
        : "+f"(d[0]), "+f"(d[1]), "+f"(d[2]), "+f"(d[3])
        : "r"(a[0]), "r"(a[1]), "r"(a[2]), "r"(a[3]), "r"(b0), "r"(b1));
}

// --------------------------- HMMA 3-split GEMM core -------------------------
// C[128x128 tile] fp32 = (Ahi+Alo) @ (Bhi+Blo)^T, lo*lo dropped.
// BK=64, 8 warps (warp 64x32), 3-stage cp.async, frag double buffer.
#define STG_SZ 65536
#define NSTG   3
#define GEMM_SMEM (NSTG * STG_SZ)

__device__ __forceinline__ void load_chunk(
    uint32_t st, const __nv_bfloat16* __restrict__ Ah,
    const __nv_bfloat16* __restrict__ Al,
    const __nv_bfloat16* __restrict__ Bh,
    const __nv_bfloat16* __restrict__ Bl,
    size_t lda, size_t ldb, int m0, int n0, size_t kofs, int tid)
{
    const int ck = tid & 7;
    const int r0 = tid >> 3;
    const size_t co = kofs + (size_t)(ck << 3);
#pragma unroll
    for (int r = r0; r < 128; r += 32) {
        const uint32_t so = (uint32_t)(r * 128 + ((ck ^ (r & 7)) << 4));
        const size_t ga = (size_t)(m0 + r) * lda + co;
        const size_t gb = (size_t)(n0 + r) * ldb + co;
        cp16(st + so,         Ah + ga);
        cp16(st + 16384 + so, Al + ga);
        cp16(st + 32768 + so, Bh + gb);
        cp16(st + 49152 + so, Bl + gb);
    }
    CP_COMMIT();
}

template<int STATS>
__device__ __forceinline__ void gemm_core(
    const __nv_bfloat16* __restrict__ Ahi, const __nv_bfloat16* __restrict__ Alo,
    const __nv_bfloat16* __restrict__ Bhi, const __nv_bfloat16* __restrict__ Blo,
    float* __restrict__ C, size_t lda, size_t ldb, size_t ldc,
    int nkc, size_t kbase, float* __restrict__ pstat, char* smem)
{
    const uint32_t sb = smem_u32(smem);
    const int tid  = threadIdx.x;
    const int wid  = tid >> 5, lane = tid & 31;
    const int m0   = blockIdx.y * 128;
    const int n0   = blockIdx.x * 128;

    const int wm = (wid & 1) * 64;
    const int wn = (wid >> 1) * 32;

    int aRow[4], aSw[4];
#pragma unroll
    for (int mt = 0; mt < 4; mt++) {
        aRow[mt] = wm + mt * 16 + (lane & 15);
        aSw[mt]  = aRow[mt] & 7;
    }
    const int ackL = lane >> 4;
    int bRow[2], bSw[2];
#pragma unroll
    for (int np = 0; np < 2; np++) {
        bRow[np] = wn + np * 16 + (lane & 7) + ((lane >> 4) << 3);
        bSw[np]  = bRow[np] & 7;
    }
    const int bckL = (lane >> 3) & 1;

    float acc[4][4][4];
#pragma unroll
    for (int i = 0; i < 4; i++)
#pragma unroll
        for (int j = 0; j < 4; j++)
#pragma unroll
            for (int e = 0; e < 4; e++) acc[i][j][e] = 0.f;

    load_chunk(sb,          Ahi, Alo, Bhi, Blo, lda, ldb, m0, n0, kbase,      tid);
    load_chunk(sb + STG_SZ, Ahi, Alo, Bhi, Blo, lda, ldb, m0, n0, kbase + 64, tid);

    uint32_t ah[2][4][4], al[2][4][4], bh[2][2][4], bl[2][2][4];

#define FRAG_LOAD(p, kk, stA, stB) do {                                          \
    _Pragma("unroll")                                                            \
    for (int mt = 0; mt < 4; mt++) {                                             \
        const uint32_t ad = (stA) + (uint32_t)(aRow[mt] * 128)                   \
                          + (uint32_t)(((2 * (kk) + ackL) ^ aSw[mt]) << 4);      \
        LDSM_X4(ah[p][mt], ad);                                                  \
        LDSM_X4(al[p][mt], ad + 16384);                                          \
    }                                                                            \
    _Pragma("unroll")                                                            \
    for (int np = 0; np < 2; np++) {                                             \
        const uint32_t bd = (stB) + (uint32_t)(bRow[np] * 128)                   \
                          + (uint32_t)(((2 * (kk) + bckL) ^ bSw[np]) << 4);      \
        LDSM_X4(bh[p][np], bd);                                                  \
        LDSM_X4(bl[p][np], bd + 16384);                                          \
    }                                                                            \
} while (0)

#pragma unroll 1
    for (int c = 0; c < nkc; c++) {
        if (c + 1 < nkc) asm volatile("cp.async.wait_group 1;" ::: "memory");
        else             asm volatile("cp.async.wait_group 0;" ::: "memory");
        __syncthreads();

        if (c + 2 < nkc)
            load_chunk(sb + (uint32_t)((c + 2) % NSTG) * STG_SZ, Ahi, Alo, Bhi, Blo,
                       lda, ldb, m0, n0, kbase + (size_t)(c + 2) * 64, tid);

        const uint32_t stA = sb + (uint32_t)(c % NSTG) * STG_SZ;
        const uint32_t stB = stA + 32768;

        FRAG_LOAD(0, 0, stA, stB);
#pragma unroll
        for (int kk = 0; kk < 4; kk++) {
            if (kk < 3) FRAG_LOAD((kk + 1) & 1, kk + 1, stA, stB);
            const int p = kk & 1;
#pragma unroll
            for (int mt = 0; mt < 4; mt++)
#pragma unroll
                for (int nt = 0; nt < 4; nt++) {
                    const int np = nt >> 1, h = (nt & 1) * 2;
                    mma16816(acc[mt][nt], ah[p][mt], bh[p][np][h], bh[p][np][h + 1]);
                    mma16816(acc[mt][nt], ah[p][mt], bl[p][np][h], bl[p][np][h + 1]);
                    mma16816(acc[mt][nt], al[p][mt], bh[p][np][h], bh[p][np][h + 1]);
                }
        }
    }
#undef FRAG_LOAD

    // store C
    const int re = lane >> 2;
    const int ce = (lane & 3) * 2;
#pragma unroll
    for (int mt = 0; mt < 4; mt++) {
#pragma unroll
        for (int nt = 0; nt < 4; nt++) {
            const size_t r  = (size_t)(m0 + wm + mt * 16 + re);
            const size_t cc = (size_t)(n0 + wn + nt * 8 + ce);
            float2 v0 = make_float2(acc[mt][nt][0], acc[mt][nt][1]);
            float2 v1 = make_float2(acc[mt][nt][2], acc[mt][nt][3]);
            *reinterpret_cast<float2*>(C + r * ldc + cc)       = v0;
            *reinterpret_cast<float2*>(C + (r + 8) * ldc + cc) = v1;
        }
    }

    if (STATS) {
        // per-CTA column partial sums / sumsq over 128 rows (deterministic)
        float s[4][2], q[4][2];
#pragma unroll
        for (int nt = 0; nt < 4; nt++)
#pragma unroll
            for (int e = 0; e < 2; e++) { s[nt][e] = 0.f; q[nt][e] = 0.f; }
#pragma unroll
        for (int mt = 0; mt < 4; mt++)
#pragma unroll
            for (int nt = 0; nt < 4; nt++)
#pragma unroll
                for (int e = 0; e < 2; e++) {
                    float v0 = acc[mt][nt][e], v1 = acc[mt][nt][e + 2];
                    s[nt][e] += v0 + v1;
                    q[nt][e] = fmaf(v0, v0, fmaf(v1, v1, q[nt][e]));
                }
#pragma unroll
        for (int off = 4; off <= 16; off <<= 1)
#pragma unroll
            for (int nt = 0; nt < 4; nt++)
#pragma unroll
                for (int e = 0; e < 2; e++) {
                    s[nt][e] += __shfl_xor_sync(0xffffffffu, s[nt][e], off);
                    q[nt][e] += __shfl_xor_sync(0xffffffffu, q[nt][e], off);
                }
        __syncthreads();                       // stages dead; reuse smem
        float* sred = reinterpret_cast<float*>(smem);  // [mh][sq][128]
        if (lane < 4) {
#pragma unroll
            for (int nt = 0; nt < 4; nt++)
#pragma unroll
                for (int e = 0; e < 2; e++) {
                    const int col = wn + nt * 8 + lane * 2 + e;
                    sred[((wid & 1) * 2 + 0) * 128 + col] = s[nt][e];
                    sred[((wid & 1) * 2 + 1) * 128 + col] = q[nt][e];
                }
        }
        __syncthreads();
        if (tid < 128) {
            pstat[tid]       = sred[0 * 128 + tid] + sred[2 * 128 + tid];
            pstat[128 + tid] = sred[1 * 128 + tid] + sred[3 * 128 + tid];
        }
    }
}

// ------------------------------ GEMM wrappers -------------------------------
__global__ void __launch_bounds__(256, 1)
fc_gemm(const __nv_bfloat16* __restrict__ Xhi, const __nv_bfloat16* __restrict__ Xlo,
        const __nv_bfloat16* __restrict__ Whi, const __nv_bfloat16* __restrict__ Wlo,
        float* __restrict__ H, float* __restrict__ pstat)
{
    extern __shared__ char smem[];
    const int f = blockIdx.z;
    const int a = f / 3, r = f - 3 * a;
    const int xi = (r == 0) ? a : (a + 1) % 3;
    const size_t XSZ = (size_t)B_ * XK, WSZ = (size_t)OD * XK, PSZ = (size_t)B_ * OD;
    gemm_core<1>(Xhi + (size_t)xi * XSZ, Xlo + (size_t)xi * XSZ,
                 Whi + (size_t)f * WSZ, Wlo + (size_t)f * WSZ,
                 H + (size_t)f * PSZ, XK, XK, OD, XK / 64, 0,
                 pstat + ((((size_t)f * 256 + blockIdx.y) * 4 + blockIdx.x) * 256),
                 smem);
}

__global__ void __launch_bounds__(256, 1)
qtk_gemm(const __nv_bfloat16* __restrict__ Thi, const __nv_bfloat16* __restrict__ Tlo,
         float* __restrict__ Spart)
{
    extern __shared__ char smem[];
    const int a = blockIdx.z >> 4, sp = blockIdx.z & 15;
    const size_t TSZ = (size_t)OD * B_;
    gemm_core<0>(Thi + (size_t)(2 * a) * TSZ,     Tlo + (size_t)(2 * a) * TSZ,
                 Thi + (size_t)(2 * a + 1) * TSZ, Tlo + (size_t)(2 * a + 1) * TSZ,
                 Spart + (size_t)(a * NSPL + sp) * OD * OD,
                 B_, B_, OD, (B_ / NSPL) / 64, (size_t)sp * (B_ / NSPL),
                 nullptr, smem);
}

__global__ void __launch_bounds__(256, 1)
av_gemm(const __nv_bfloat16* __restrict__ Phi, const __nv_bfloat16* __restrict__ Plo,
        const __nv_bfloat16* __restrict__ Athi, const __nv_bfloat16* __restrict__ Atlo,
        float* __restrict__ out)
{
    extern __shared__ char smem[];
    const int a = blockIdx.z;
    const size_t PSZ = (size_t)B_ * OD;
    gemm_core<0>(Phi + (size_t)(3 * a + 2) * PSZ, Plo + (size_t)(3 * a + 2) * PSZ,
                 Athi + (size_t)a * OD * OD, Atlo + (size_t)a * OD * OD,
                 out + (size_t)a * PSZ, OD, OD, OD, OD / 64, 0, nullptr, smem);
}

// ----------------------- fp32 -> bf16 hi/lo split ---------------------------
__global__ void __launch_bounds__(256)
split_planes(const float4* __restrict__ in, __nv_bfloat162* __restrict__ hi,
             __nv_bfloat162* __restrict__ lo, int n4)
{
    int i = blockIdx.x * 256 + threadIdx.x;
    if (i >= n4) return;
    float4 v = in[i];
    __nv_bfloat16 h0 = __float2bfloat16_rn(v.x), h1 = __float2bfloat16_rn(v.y);
    __nv_bfloat16 h2 = __float2bfloat16_rn(v.z), h3 = __float2bfloat16_rn(v.w);
    __nv_bfloat16 l0 = __float2bfloat16_rn(v.x - __bfloat162float(h0));
    __nv_bfloat16 l1 = __float2bfloat16_rn(v.y - __bfloat162float(h1));
    __nv_bfloat16 l2 = __float2bfloat16_rn(v.z - __bfloat162float(h2));
    __nv_bfloat16 l3 = __float2bfloat16_rn(v.w - __bfloat162float(h3));
    hi[2 * i]     = __halves2bfloat162(h0, h1);
    hi[2 * i + 1] = __halves2bfloat162(h2, h3);
    lo[2 * i]     = __halves2bfloat162(l0, l1);
    lo[2 * i + 1] = __halves2bfloat162(l2, l3);
}

// -------------------- stats reduce: partials -> mu, rstd --------------------
__global__ void __launch_bounds__(512)
stats2(const float* __restrict__ pstat)
{
    const int f = blockIdx.x, col = threadIdx.x;
    const int nx = col >> 7, cl = col & 127;
    float s = 0.f, q = 0.f;
    for (int my = 0; my < 256; my++) {
        const size_t base = (((size_t)f * 256 + my) * 4 + nx) * 256;
        s += pstat[base + cl];
        q += pstat[base + 128 + cl];
    }
    const float mu  = s * (1.f / B_);
    const float var = q * (1.f / B_) - mu * mu;
    g_mu  [f * OD + col] = mu;
    g_rstd[f * OD + col] = rsqrtf(var + 1e-5f);
}

// -------- BN + ReLU -> bf16 planes; Q/K written transposed, V normal --------
__global__ void __launch_bounds__(256)
bn_fuse(const float* __restrict__ H, const float* __restrict__ gammas,
        const float* __restrict__ betas)
{
    const int f = blockIdx.z;
    const int a = f / 3, r = f - 3 * a;
    const int c0 = blockIdx.x * 32;
    const size_t b0 = (size_t)blockIdx.y * 32;
    const int tx = threadIdx.x, ty = threadIdx.y;
    const int col = c0 + tx;
    const float mu = g_mu[f * OD + col], rs = g_rstd[f * OD + col];
    const float ga = gammas[(size_t)f * OD + col], be = betas[(size_t)f * OD + col];
    const float* Hp = H + (size_t)f * B_ * OD;

    __shared__ float t[32][33];

    if (r == 2) {
        __nv_bfloat16* Ph = g_Phi + (size_t)f * B_ * OD;
        __nv_bfloat16* Pl = g_Plo + (size_t)f * B_ * OD;
#pragma unroll
        for (int i = 0; i < 32; i += 8) {
            const size_t off = (b0 + ty + i) * OD + col;
            float v = Hp[off];
            v = fmaxf(fmaf((v - mu) * rs, ga, be), 0.f);
            __nv_bfloat16 h = __float2bfloat16_rn(v);
            Ph[off] = h;
            Pl[off] = __float2bfloat16_rn(v - __bfloat162float(h));
        }
    } else {
        const int slot = 2 * a + r;
#pragma unroll
        for (int i = 0; i < 32; i += 8) {
            float v = Hp[(b0 + ty + i) * OD + col];
            t[ty + i][tx] = fmaxf(fmaf((v - mu) * rs, ga, be), 0.f);
        }
        __syncthreads();
        __nv_bfloat16* Th = g_Thi + (size_t)slot * OD * B_;
        __nv_bfloat16* Tl = g_Tlo + (size_t)slot * OD * B_;
#pragma unroll
        for (int i = 0; i < 32; i += 8) {
            const float v = t[tx][ty + i];
            const size_t off = (size_t)(c0 + ty + i) * B_ + b0 + tx;
            __nv_bfloat16 h = __float2bfloat16_rn(v);
            Th[off] = h;
            Tl[off] = __float2bfloat16_rn(v - __bfloat162float(h));
        }
    }
}

// --------- reduce split-K partials + row softmax -> attn bf16 planes --------
__global__ void __launch_bounds__(256)
softmax_rows()
{
    const int i = blockIdx.x, a = blockIdx.y, tid = threadIdx.x;
    __shared__ float red[256];

    const float* Sp = g_Spart + (size_t)a * NSPL * OD * OD + (size_t)i * OD;
    float v0 = 0.f, v1 = 0.f;
#pragma unroll
    for (int s = 0; s < NSPL; s++) {
        v0 += Sp[(size_t)s * OD * OD + tid];
        v1 += Sp[(size_t)s * OD * OD + tid + 256];
    }
    v0 *= 0.03125f;
    v1 *= 0.03125f;

    red[tid] = fmaxf(v0, v1);
    __syncthreads();
    for (int o = 128; o > 0; o >>= 1) {
        if (tid < o) red[tid] = fmaxf(red[tid], red[tid + o]);
        __syncthreads();
    }
    const float m = red[0];
    __syncthreads();
    const float e0 = expf(v0 - m), e1 = expf(v1 - m);
    red[tid] = e0 + e1;
    __syncthreads();
    for (int o = 128; o > 0; o >>= 1) {
        if (tid < o) red[tid] += red[tid + o];
        __syncthreads();
    }
    const float inv = 1.f / red[0];
    const float p0 = e0 * inv, p1 = e1 * inv;

    const size_t base = (size_t)a * OD * OD + (size_t)i * OD;
    __nv_bfloat16 h0 = __float2bfloat16_rn(p0), h1 = __float2bfloat16_rn(p1);
    g_Athi[base + tid]       = h0;
    g_Athi[base + tid + 256] = h1;
    g_Atlo[base + tid]       = __float2bfloat16_rn(p0 - __bfloat162float(h0));
    g_Atlo[base + tid + 256] = __float2bfloat16_rn(p1 - __bfloat162float(h1));
}

// ---------------------------------------------------------------------------
extern "C" void kernel_launch(void* const* d_in, const int* in_sizes, int n_in,
                              void* d_out, int out_size)
{
    (void)in_sizes; (void)n_in; (void)out_size;
    const float* X[3] = { (const float*)d_in[0], (const float*)d_in[1],
                          (const float*)d_in[2] };
    const float* Ws     = (const float*)d_in[3];
    const float* gammas = (const float*)d_in[5];
    const float* betas  = (const float*)d_in[6];
    float* out = (float*)d_out;

    float *Hp, *Spartp, *Pstatp;
    __nv_bfloat16 *Xhi, *Xlo, *Whi, *Wlo, *Phi, *Plo, *Thi, *Tlo, *Athi, *Atlo;
    cudaGetSymbolAddress((void**)&Hp, g_H);
    cudaGetSymbolAddress((void**)&Spartp, g_Spart);
    cudaGetSymbolAddress((void**)&Pstatp, g_Pstat);
    cudaGetSymbolAddress((void**)&Xhi, g_Xhi);
    cudaGetSymbolAddress((void**)&Xlo, g_Xlo);
    cudaGetSymbolAddress((void**)&Whi, g_Whi);
    cudaGetSymbolAddress((void**)&Wlo, g_Wlo);
    cudaGetSymbolAddress((void**)&Phi, g_Phi);
    cudaGetSymbolAddress((void**)&Plo, g_Plo);
    cudaGetSymbolAddress((void**)&Thi, g_Thi);
    cudaGetSymbolAddress((void**)&Tlo, g_Tlo);
    cudaGetSymbolAddress((void**)&Athi, g_Athi);
    cudaGetSymbolAddress((void**)&Atlo, g_Atlo);

    cudaFuncSetAttribute(fc_gemm,  cudaFuncAttributeMaxDynamicSharedMemorySize, GEMM_SMEM);
    cudaFuncSetAttribute(qtk_gemm, cudaFuncAttributeMaxDynamicSharedMemorySize, GEMM_SMEM);
    cudaFuncSetAttribute(av_gemm,  cudaFuncAttributeMaxDynamicSharedMemorySize, GEMM_SMEM);

    const size_t XSZ = (size_t)B_ * XK;
    const size_t WSZ = (size_t)OD * XK;
    const size_t PSZ = (size_t)B_ * OD;

    // 1. split inputs + weights to bf16 hi/lo planes
    {
        int n4 = (int)(XSZ / 4);
        for (int i = 0; i < 3; i++)
            split_planes<<<(n4 + 255) / 256, 256>>>(
                (const float4*)X[i], (__nv_bfloat162*)(Xhi + i * XSZ),
                (__nv_bfloat162*)(Xlo + i * XSZ), n4);
        int w4 = (int)((size_t)NFC * WSZ / 4);
        split_planes<<<(w4 + 255) / 256, 256>>>(
            (const float4*)Ws, (__nv_bfloat162*)Whi, (__nv_bfloat162*)Wlo, w4);
    }

    // 2. all nine FC GEMMs in one launch (stats fused into epilogue)
    fc_gemm<<<dim3(OD / 128, B_ / 128, NFC), 256, GEMM_SMEM>>>(
        Xhi, Xlo, Whi, Wlo, Hp, Pstatp);

    // 3. stats reduce + BN/ReLU (V normal planes, Q/K transposed planes)
    stats2<<<NFC, 512>>>(Pstatp);
    bn_fuse<<<dim3(OD / 32, B_ / 32, NFC), dim3(32, 8)>>>(Hp, gammas, betas);

    // 4. all QtK split-K GEMMs in one launch
    qtk_gemm<<<dim3(OD / 128, OD / 128, 3 * NSPL), 256, GEMM_SMEM>>>(
        Thi, Tlo, Spartp);

    // 5. softmax (reduces 16 partials) -> attn bf16 planes
    softmax_rows<<<dim3(OD, 3), 256>>>();

    // 6. all AV GEMMs in one launch
    av_gemm<<<dim3(OD / 128, B_ / 128, 3), 256, GEMM_SMEM>>>(
        Phi, Plo, Athi, Atlo, out);
}

// round 5
// speedup vs baseline: 3.2388x; 1.0206x over previous
#include <cuda_runtime.h>
#include <cuda_bf16.h>
#include <cstdint>
#include <cstddef>

#define B_    32768
#define XK    1024
#define OD    512
#define NFC   9
#define NSPL  16

// ------------------------- scratch (device globals) ------------------------
__device__ __align__(128) float g_H[(size_t)NFC * B_ * OD];
__device__ __align__(128) __nv_bfloat16 g_Xhi[(size_t)3 * B_ * XK], g_Xlo[(size_t)3 * B_ * XK];
__device__ __align__(128) __nv_bfloat16 g_Whi[(size_t)NFC * OD * XK], g_Wlo[(size_t)NFC * OD * XK];
__device__ __align__(128) __nv_bfloat16 g_Phi[(size_t)NFC * B_ * OD], g_Plo[(size_t)NFC * B_ * OD];
__device__ __align__(128) __nv_bfloat16 g_Thi[(size_t)6 * OD * B_], g_Tlo[(size_t)6 * OD * B_];
__device__ __align__(128) float g_Spart[(size_t)3 * NSPL * OD * OD];
__device__ __align__(128) __nv_bfloat16 g_Athi[(size_t)3 * OD * OD], g_Atlo[(size_t)3 * OD * OD];
__device__ __align__(128) float g_Pstat[(size_t)NFC * 256 * 4 * 256]; // [f][my][nx][{s,q}x128]
__device__ float g_mu[NFC * OD], g_rstd[NFC * OD];

// ------------------------------ PTX helpers --------------------------------
__device__ __forceinline__ uint32_t smem_u32(const void* p) {
    uint32_t a;
    asm("{ .reg .u64 t; cvta.to.shared.u64 t, %1; cvt.u32.u64 %0, t; }" : "=r"(a) : "l"(p));
    return a;
}
__device__ __forceinline__ void cp16(uint32_t sa, const void* g) {
    asm volatile("cp.async.cg.shared.global [%0], [%1], 16;" :: "r"(sa), "l"(g));
}
#define CP_COMMIT() asm volatile("cp.async.commit_group;" ::: "memory")

#define LDSM_X4(r, a) asm volatile(                                          \
    "ldmatrix.sync.aligned.m8n8.x4.shared.b16 {%0,%1,%2,%3}, [%4];"          \
    : "=r"((r)[0]), "=r"((r)[1]), "=r"((r)[2]), "=r"((r)[3]) : "r"(a))

__device__ __forceinline__ void mma16816(float* d, const uint32_t* a,
                                         uint32_t b0, uint32_t b1) {
    asm volatile(
        "mma.sync.aligned.m16n8k16.row.col.f32.bf16.bf16.f32 "
        "{%0,%1,%2,%3}, {%4,%5,%6,%7}, {%8,%9}, {%0,%1,%2,%3};"
        : "+f"(d[0]), "+f"(d[1]), "+f"(d[2]), "+f"(d[3])
        : "r"(a[0]), "r"(a[1]), "r"(a[2]), "r"(a[3]), "r"(b0), "r"(b1));
}

// --------------------------- HMMA 3-split GEMM core -------------------------
// C[128x128 tile] fp32 = (Ahi+Alo) @ (Bhi+Blo)^T, lo*lo dropped.
// BK=32; hi/lo interleaved in one 128B smem row (chunks 0-3 hi, 4-7 lo),
// xor-swizzled; 8 warps (warp 64x32), 3-stage cp.async, 2 CTAs/SM.
#define STG_SZ 32768
#define NSTG   3
#define GEMM_SMEM (NSTG * STG_SZ)

__device__ __forceinline__ void load_chunk(
    uint32_t st, const __nv_bfloat16* __restrict__ Ah,
    const __nv_bfloat16* __restrict__ Al,
    const __nv_bfloat16* __restrict__ Bh,
    const __nv_bfloat16* __restrict__ Bl,
    size_t lda, size_t ldb, int m0, int n0, size_t kofs, int tid)
{
    const int ck = tid & 7;              // chunk slot: 0-3 hi, 4-7 lo
    const int r0 = tid >> 3;             // 0..31
    const int kc = ck & 3;               // 16B chunk within 32-elem k
    const size_t co = kofs + (size_t)(kc << 3);
    const __nv_bfloat16* As = (ck >= 4) ? Al : Ah;
    const __nv_bfloat16* Bs = (ck >= 4) ? Bl : Bh;
#pragma unroll
    for (int r = r0; r < 128; r += 32) {
        const uint32_t so = (uint32_t)(r * 128 + ((ck ^ (r & 7)) << 4));
        cp16(st + so,         As + (size_t)(m0 + r) * lda + co);
        cp16(st + 16384 + so, Bs + (size_t)(n0 + r) * ldb + co);
    }
    CP_COMMIT();
}

template<int STATS>
__device__ __forceinline__ void gemm_core(
    const __nv_bfloat16* __restrict__ Ahi, const __nv_bfloat16* __restrict__ Alo,
    const __nv_bfloat16* __restrict__ Bhi, const __nv_bfloat16* __restrict__ Blo,
    float* __restrict__ C, size_t lda, size_t ldb, size_t ldc,
    int nkc, size_t kbase, float* __restrict__ pstat, char* smem)
{
    const uint32_t sb = smem_u32(smem);
    const int tid  = threadIdx.x;
    const int wid  = tid >> 5, lane = tid & 31;
    const int m0   = blockIdx.y * 128;
    const int n0   = blockIdx.x * 128;

    const int wm = (wid & 1) * 64;
    const int wn = (wid >> 1) * 32;

    int aRow[4], aSw[4];
#pragma unroll
    for (int mt = 0; mt < 4; mt++) {
        aRow[mt] = wm + mt * 16 + (lane & 15);
        aSw[mt]  = aRow[mt] & 7;
    }
    const int ackL = lane >> 4;          // 0/1
    int bRow[2], bSw[2];
#pragma unroll
    for (int np = 0; np < 2; np++) {
        bRow[np] = wn + np * 16 + (lane & 7) + ((lane >> 4) << 3);
        bSw[np]  = bRow[np] & 7;
    }
    const int bckL = (lane >> 3) & 1;

    float acc[4][4][4];
#pragma unroll
    for (int i = 0; i < 4; i++)
#pragma unroll
        for (int j = 0; j < 4; j++)
#pragma unroll
            for (int e = 0; e < 4; e++) acc[i][j][e] = 0.f;

    load_chunk(sb,          Ahi, Alo, Bhi, Blo, lda, ldb, m0, n0, kbase,      tid);
    load_chunk(sb + STG_SZ, Ahi, Alo, Bhi, Blo, lda, ldb, m0, n0, kbase + 32, tid);

#pragma unroll 1
    for (int c = 0; c < nkc; c++) {
        if (c + 1 < nkc) asm volatile("cp.async.wait_group 1;" ::: "memory");
        else             asm volatile("cp.async.wait_group 0;" ::: "memory");
        __syncthreads();

        if (c + 2 < nkc)
            load_chunk(sb + (uint32_t)((c + 2) % NSTG) * STG_SZ, Ahi, Alo, Bhi, Blo,
                       lda, ldb, m0, n0, kbase + (size_t)(c + 2) * 32, tid);

        const uint32_t stA = sb + (uint32_t)(c % NSTG) * STG_SZ;
        const uint32_t stB = stA + 16384;

#pragma unroll
        for (int kk = 0; kk < 2; kk++) {
            uint32_t ah[4][4], al[4][4], bh[2][4], bl[2][4];
            const int ca = 2 * kk + ackL;
            const int cb = 2 * kk + bckL;
#pragma unroll
            for (int mt = 0; mt < 4; mt++) {
                const uint32_t base = stA + (uint32_t)(aRow[mt] * 128);
                LDSM_X4(ah[mt], base + (uint32_t)((ca       ^ aSw[mt]) << 4));
                LDSM_X4(al[mt], base + (uint32_t)(((ca + 4) ^ aSw[mt]) << 4));
            }
#pragma unroll
            for (int np = 0; np < 2; np++) {
                const uint32_t base = stB + (uint32_t)(bRow[np] * 128);
                LDSM_X4(bh[np], base + (uint32_t)((cb       ^ bSw[np]) << 4));
                LDSM_X4(bl[np], base + (uint32_t)(((cb + 4) ^ bSw[np]) << 4));
            }
#pragma unroll
            for (int mt = 0; mt < 4; mt++)
#pragma unroll
                for (int nt = 0; nt < 4; nt++) {
                    const int np = nt >> 1, h = (nt & 1) * 2;
                    mma16816(acc[mt][nt], ah[mt], bh[np][h], bh[np][h + 1]);
                    mma16816(acc[mt][nt], ah[mt], bl[np][h], bl[np][h + 1]);
                    mma16816(acc[mt][nt], al[mt], bh[np][h], bh[np][h + 1]);
                }
        }
    }

    // store C
    const int re = lane >> 2;
    const int ce = (lane & 3) * 2;
#pragma unroll
    for (int mt = 0; mt < 4; mt++) {
#pragma unroll
        for (int nt = 0; nt < 4; nt++) {
            const size_t r  = (size_t)(m0 + wm + mt * 16 + re);
            const size_t cc = (size_t)(n0 + wn + nt * 8 + ce);
            float2 v0 = make_float2(acc[mt][nt][0], acc[mt][nt][1]);
            float2 v1 = make_float2(acc[mt][nt][2], acc[mt][nt][3]);
            *reinterpret_cast<float2*>(C + r * ldc + cc)       = v0;
            *reinterpret_cast<float2*>(C + (r + 8) * ldc + cc) = v1;
        }
    }

    if (STATS) {
        float s[4][2], q[4][2];
#pragma unroll
        for (int nt = 0; nt < 4; nt++)
#pragma unroll
            for (int e = 0; e < 2; e++) { s[nt][e] = 0.f; q[nt][e] = 0.f; }
#pragma unroll
        for (int mt = 0; mt < 4; mt++)
#pragma unroll
            for (int nt = 0; nt < 4; nt++)
#pragma unroll
                for (int e = 0; e < 2; e++) {
                    float v0 = acc[mt][nt][e], v1 = acc[mt][nt][e + 2];
                    s[nt][e] += v0 + v1;
                    q[nt][e] = fmaf(v0, v0, fmaf(v1, v1, q[nt][e]));
                }
#pragma unroll
        for (int off = 4; off <= 16; off <<= 1)
#pragma unroll
            for (int nt = 0; nt < 4; nt++)
#pragma unroll
                for (int e = 0; e < 2; e++) {
                    s[nt][e] += __shfl_xor_sync(0xffffffffu, s[nt][e], off);
                    q[nt][e] += __shfl_xor_sync(0xffffffffu, q[nt][e], off);
                }
        __syncthreads();
        float* sred = reinterpret_cast<float*>(smem);
        if (lane < 4) {
#pragma unroll
            for (int nt = 0; nt < 4; nt++)
#pragma unroll
                for (int e = 0; e < 2; e++) {
                    const int col = wn + nt * 8 + lane * 2 + e;
                    sred[((wid & 1) * 2 + 0) * 128 + col] = s[nt][e];
                    sred[((wid & 1) * 2 + 1) * 128 + col] = q[nt][e];
                }
        }
        __syncthreads();
        if (tid < 128) {
            pstat[tid]       = sred[0 * 128 + tid] + sred[2 * 128 + tid];
            pstat[128 + tid] = sred[1 * 128 + tid] + sred[3 * 128 + tid];
        }
    }
}

// ------------------------------ GEMM wrappers -------------------------------
__global__ void __launch_bounds__(256, 2)
fc_gemm(const __nv_bfloat16* __restrict__ Xhi, const __nv_bfloat16* __restrict__ Xlo,
        const __nv_bfloat16* __restrict__ Whi, const __nv_bfloat16* __restrict__ Wlo,
        float* __restrict__ H, float* __restrict__ pstat)
{
    extern __shared__ char smem[];
    const int f = blockIdx.z;
    const int a = f / 3, r = f - 3 * a;
    const int xi = (r == 0) ? a : (a + 1) % 3;
    const size_t XSZ = (size_t)B_ * XK, WSZ = (size_t)OD * XK, PSZ = (size_t)B_ * OD;
    gemm_core<1>(Xhi + (size_t)xi * XSZ, Xlo + (size_t)xi * XSZ,
                 Whi + (size_t)f * WSZ, Wlo + (size_t)f * WSZ,
                 H + (size_t)f * PSZ, XK, XK, OD, XK / 32, 0,
                 pstat + ((((size_t)f * 256 + blockIdx.y) * 4 + blockIdx.x) * 256),
                 smem);
}

__global__ void __launch_bounds__(256, 2)
qtk_gemm(const __nv_bfloat16* __restrict__ Thi, const __nv_bfloat16* __restrict__ Tlo,
         float* __restrict__ Spart)
{
    extern __shared__ char smem[];
    const int a = blockIdx.z >> 4, sp = blockIdx.z & 15;
    const size_t TSZ = (size_t)OD * B_;
    gemm_core<0>(Thi + (size_t)(2 * a) * TSZ,     Tlo + (size_t)(2 * a) * TSZ,
                 Thi + (size_t)(2 * a + 1) * TSZ, Tlo + (size_t)(2 * a + 1) * TSZ,
                 Spart + (size_t)(a * NSPL + sp) * OD * OD,
                 B_, B_, OD, (B_ / NSPL) / 32, (size_t)sp * (B_ / NSPL),
                 nullptr, smem);
}

__global__ void __launch_bounds__(256, 2)
av_gemm(const __nv_bfloat16* __restrict__ Phi, const __nv_bfloat16* __restrict__ Plo,
        const __nv_bfloat16* __restrict__ Athi, const __nv_bfloat16* __restrict__ Atlo,
        float* __restrict__ out)
{
    extern __shared__ char smem[];
    const int a = blockIdx.z;
    const size_t PSZ = (size_t)B_ * OD;
    gemm_core<0>(Phi + (size_t)(3 * a + 2) * PSZ, Plo + (size_t)(3 * a + 2) * PSZ,
                 Athi + (size_t)a * OD * OD, Atlo + (size_t)a * OD * OD,
                 out + (size_t)a * PSZ, OD, OD, OD, OD / 32, 0, nullptr, smem);
}

// ----------------------- fp32 -> bf16 hi/lo split ---------------------------
__global__ void __launch_bounds__(256)
split_planes(const float4* __restrict__ in, __nv_bfloat162* __restrict__ hi,
             __nv_bfloat162* __restrict__ lo, int n4)
{
    int i = blockIdx.x * 256 + threadIdx.x;
    if (i >= n4) return;
    float4 v = in[i];
    __nv_bfloat16 h0 = __float2bfloat16_rn(v.x), h1 = __float2bfloat16_rn(v.y);
    __nv_bfloat16 h2 = __float2bfloat16_rn(v.z), h3 = __float2bfloat16_rn(v.w);
    __nv_bfloat16 l0 = __float2bfloat16_rn(v.x - __bfloat162float(h0));
    __nv_bfloat16 l1 = __float2bfloat16_rn(v.y - __bfloat162float(h1));
    __nv_bfloat16 l2 = __float2bfloat16_rn(v.z - __bfloat162float(h2));
    __nv_bfloat16 l3 = __float2bfloat16_rn(v.w - __bfloat162float(h3));
    hi[2 * i]     = __halves2bfloat162(h0, h1);
    hi[2 * i + 1] = __halves2bfloat162(h2, h3);
    lo[2 * i]     = __halves2bfloat162(l0, l1);
    lo[2 * i + 1] = __halves2bfloat162(l2, l3);
}

// -------------------- stats reduce: partials -> mu, rstd --------------------
__global__ void __launch_bounds__(512)
stats2(const float* __restrict__ pstat)
{
    const int f = blockIdx.x, col = threadIdx.x;
    const int nx = col >> 7, cl = col & 127;
    float s = 0.f, q = 0.f;
    for (int my = 0; my < 256; my++) {
        const size_t base = (((size_t)f * 256 + my) * 4 + nx) * 256;
        s += pstat[base + cl];
        q += pstat[base + 128 + cl];
    }
    const float mu  = s * (1.f / B_);
    const float var = q * (1.f / B_) - mu * mu;
    g_mu  [f * OD + col] = mu;
    g_rstd[f * OD + col] = rsqrtf(var + 1e-5f);
}

// -------- BN + ReLU -> bf16 planes; Q/K written transposed, V normal --------
__global__ void __launch_bounds__(256)
bn_fuse(const float* __restrict__ H, const float* __restrict__ gammas,
        const float* __restrict__ betas)
{
    const int f = blockIdx.z;
    const int a = f / 3, r = f - 3 * a;
    const int c0 = blockIdx.x * 32;
    const size_t b0 = (size_t)blockIdx.y * 32;
    const int tx = threadIdx.x, ty = threadIdx.y;
    const int col = c0 + tx;
    const float mu = g_mu[f * OD + col], rs = g_rstd[f * OD + col];
    const float ga = gammas[(size_t)f * OD + col], be = betas[(size_t)f * OD + col];
    const float* Hp = H + (size_t)f * B_ * OD;

    __shared__ float t[32][33];

    if (r == 2) {
        __nv_bfloat16* Ph = g_Phi + (size_t)f * B_ * OD;
        __nv_bfloat16* Pl = g_Plo + (size_t)f * B_ * OD;
#pragma unroll
        for (int i = 0; i < 32; i += 8) {
            const size_t off = (b0 + ty + i) * OD + col;
            float v = Hp[off];
            v = fmaxf(fmaf((v - mu) * rs, ga, be), 0.f);
            __nv_bfloat16 h = __float2bfloat16_rn(v);
            Ph[off] = h;
            Pl[off] = __float2bfloat16_rn(v - __bfloat162float(h));
        }
    } else {
        const int slot = 2 * a + r;
#pragma unroll
        for (int i = 0; i < 32; i += 8) {
            float v = Hp[(b0 + ty + i) * OD + col];
            t[ty + i][tx] = fmaxf(fmaf((v - mu) * rs, ga, be), 0.f);
        }
        __syncthreads();
        __nv_bfloat16* Th = g_Thi + (size_t)slot * OD * B_;
        __nv_bfloat16* Tl = g_Tlo + (size_t)slot * OD * B_;
#pragma unroll
        for (int i = 0; i < 32; i += 8) {
            const float v = t[tx][ty + i];
            const size_t off = (size_t)(c0 + ty + i) * B_ + b0 + tx;
            __nv_bfloat16 h = __float2bfloat16_rn(v);
            Th[off] = h;
            Tl[off] = __float2bfloat16_rn(v - __bfloat162float(h));
        }
    }
}

// --------- reduce split-K partials + row softmax -> attn bf16 planes --------
__global__ void __launch_bounds__(256)
softmax_rows()
{
    const int i = blockIdx.x, a = blockIdx.y, tid = threadIdx.x;
    __shared__ float red[256];

    const float* Sp = g_Spart + (size_t)a * NSPL * OD * OD + (size_t)i * OD;
    float v0 = 0.f, v1 = 0.f;
#pragma unroll
    for (int s = 0; s < NSPL; s++) {
        v0 += Sp[(size_t)s * OD * OD + tid];
        v1 += Sp[(size_t)s * OD * OD + tid + 256];
    }
    v0 *= 0.03125f;
    v1 *= 0.03125f;

    red[tid] = fmaxf(v0, v1);
    __syncthreads();
    for (int o = 128; o > 0; o >>= 1) {
        if (tid < o) red[tid] = fmaxf(red[tid], red[tid + o]);
        __syncthreads();
    }
    const float m = red[0];
    __syncthreads();
    const float e0 = expf(v0 - m), e1 = expf(v1 - m);
    red[tid] = e0 + e1;
    __syncthreads();
    for (int o = 128; o > 0; o >>= 1) {
        if (tid < o) red[tid] += red[tid + o];
        __syncthreads();
    }
    const float inv = 1.f / red[0];
    const float p0 = e0 * inv, p1 = e1 * inv;

    const size_t base = (size_t)a * OD * OD + (size_t)i * OD;
    __nv_bfloat16 h0 = __float2bfloat16_rn(p0), h1 = __float2bfloat16_rn(p1);
    g_Athi[base + tid]       = h0;
    g_Athi[base + tid + 256] = h1;
    g_Atlo[base + tid]       = __float2bfloat16_rn(p0 - __bfloat162float(h0));
    g_Atlo[base + tid + 256] = __float2bfloat16_rn(p1 - __bfloat162float(h1));
}

// ---------------------------------------------------------------------------
extern "C" void kernel_launch(void* const* d_in, const int* in_sizes, int n_in,
                              void* d_out, int out_size)
{
    (void)in_sizes; (void)n_in; (void)out_size;
    const float* X[3] = { (const float*)d_in[0], (const float*)d_in[1],
                          (const float*)d_in[2] };
    const float* Ws     = (const float*)d_in[3];
    const float* gammas = (const float*)d_in[5];
    const float* betas  = (const float*)d_in[6];
    float* out = (float*)d_out;

    float *Hp, *Spartp, *Pstatp;
    __nv_bfloat16 *Xhi, *Xlo, *Whi, *Wlo, *Phi, *Plo, *Thi, *Tlo, *Athi, *Atlo;
    cudaGetSymbolAddress((void**)&Hp, g_H);
    cudaGetSymbolAddress((void**)&Spartp, g_Spart);
    cudaGetSymbolAddress((void**)&Pstatp, g_Pstat);
    cudaGetSymbolAddress((void**)&Xhi, g_Xhi);
    cudaGetSymbolAddress((void**)&Xlo, g_Xlo);
    cudaGetSymbolAddress((void**)&Whi, g_Whi);
    cudaGetSymbolAddress((void**)&Wlo, g_Wlo);
    cudaGetSymbolAddress((void**)&Phi, g_Phi);
    cudaGetSymbolAddress((void**)&Plo, g_Plo);
    cudaGetSymbolAddress((void**)&Thi, g_Thi);
    cudaGetSymbolAddress((void**)&Tlo, g_Tlo);
    cudaGetSymbolAddress((void**)&Athi, g_Athi);
    cudaGetSymbolAddress((void**)&Atlo, g_Atlo);

    cudaFuncSetAttribute(fc_gemm,  cudaFuncAttributeMaxDynamicSharedMemorySize, GEMM_SMEM);
    cudaFuncSetAttribute(qtk_gemm, cudaFuncAttributeMaxDynamicSharedMemorySize, GEMM_SMEM);
    cudaFuncSetAttribute(av_gemm,  cudaFuncAttributeMaxDynamicSharedMemorySize, GEMM_SMEM);

    const size_t XSZ = (size_t)B_ * XK;
    const size_t WSZ = (size_t)OD * XK;

    // 1. split inputs + weights to bf16 hi/lo planes
    {
        int n4 = (int)(XSZ / 4);
        for (int i = 0; i < 3; i++)
            split_planes<<<(n4 + 255) / 256, 256>>>(
                (const float4*)X[i], (__nv_bfloat162*)(Xhi + i * XSZ),
                (__nv_bfloat162*)(Xlo + i * XSZ), n4);
        int w4 = (int)((size_t)NFC * WSZ / 4);
        split_planes<<<(w4 + 255) / 256, 256>>>(
            (const float4*)Ws, (__nv_bfloat162*)Whi, (__nv_bfloat162*)Wlo, w4);
    }

    // 2. all nine FC GEMMs in one launch (stats fused into epilogue)
    fc_gemm<<<dim3(OD / 128, B_ / 128, NFC), 256, GEMM_SMEM>>>(
        Xhi, Xlo, Whi, Wlo, Hp, Pstatp);

    // 3. stats reduce + BN/ReLU (V normal planes, Q/K transposed planes)
    stats2<<<NFC, 512>>>(Pstatp);
    bn_fuse<<<dim3(OD / 32, B_ / 32, NFC), dim3(32, 8)>>>(Hp, gammas, betas);

    // 4. all QtK split-K GEMMs in one launch
    qtk_gemm<<<dim3(OD / 128, OD / 128, 3 * NSPL), 256, GEMM_SMEM>>>(
        Thi, Tlo, Spartp);

    // 5. softmax (reduces 16 partials) -> attn bf16 planes
    softmax_rows<<<dim3(OD, 3), 256>>>();

    // 6. all AV GEMMs in one launch
    av_gemm<<<dim3(OD / 128, B_ / 128, 3), 256, GEMM_SMEM>>>(
        Phi, Plo, Athi, Atlo, out);
}